// round 3
// baseline (speedup 1.0000x reference)
#include <cuda_runtime.h>
#include <cstdint>
#include <math.h>

// ---------------- problem constants ----------------
#define U_N   10000
#define G_N   3000
#define I_N   8000
#define D_N   32
#define B_N   4096
#define LM    20

// ---------------- scratch layout (floats) ----------------
// one big __device__ array; all offsets multiple of 4 (16B aligned)
constexpr int OFF_UI_A = 0;        // 18000*32 = 576000   (holds e2 of UI conv at end)
constexpr int OFF_UI_B = 576000;   // 576000
constexpr int OFF_USUM = 1152000;  // 320000  sum of user layers (UI)
constexpr int OFF_ISUM = 1472000;  // 256000  sum of item layers (UI)
constexpr int OFF_UM   = 1728000;  // 320000  user mean (later reused as y2 of social)
constexpr int OFF_IEU  = 2048000;  // 256000  item_emb_for_user
constexpr int OFF_GI_A = 2304000;  // 11000*32 = 352000
constexpr int OFF_GI_B = 2656000;  // 352000
constexpr int OFF_GSUM = 3008000;  // 96000   sum of g_layers
constexpr int OFF_GIIS = 3104000;  // 256000  sum of GI item layers
constexpr int OFF_GSCR = 3360000;  // 96000   scratch for odd g_layers spmm
constexpr int OFF_GEMB = 3456000;  // 96000   g_emb
constexpr int OFF_IM   = 3552000;  // 256000  i_emb (later reused as y2 of item social)
constexpr int OFF_YS   = 3808000;  // 320000  y1 of user social
constexpr int OFF_ACCU = 4128000;  // 320000  user social accumulator
constexpr int OFF_YI   = 4448000;  // 256000  y1 of item social
constexpr int OFF_ACCI = 4704000;  // 256000  item social accumulator
constexpr int OFF_GUL  = 4960000;  // 96000   group_userlayer
constexpr int OFF_W    = 5056000;  // 6400    gate outputs (2G used)
constexpr int OFF_GF   = 5062400;  // 96000   group_final
constexpr int SCRATCH_TOTAL = 5158400;   // ~20.6 MB

__device__ float d_scratch[SCRATCH_TOTAL];

// ---------------- elementwise helpers (float4) ----------------
__global__ void k_zero4(float4* p, int n4) {
    int i = blockIdx.x * blockDim.x + threadIdx.x;
    if (i < n4) p[i] = make_float4(0.f, 0.f, 0.f, 0.f);
}
__global__ void k_copy4(float4* d, const float4* __restrict__ s, int n4) {
    int i = blockIdx.x * blockDim.x + threadIdx.x;
    if (i < n4) d[i] = s[i];
}
__global__ void k_scale4(float4* d, const float4* __restrict__ s, float a, int n4) {
    int i = blockIdx.x * blockDim.x + threadIdx.x;
    if (i < n4) { float4 v = s[i]; d[i] = make_float4(a*v.x, a*v.y, a*v.z, a*v.w); }
}
__global__ void k_axpy4(float4* d, const float4* __restrict__ s, int n4) {
    int i = blockIdx.x * blockDim.x + threadIdx.x;
    if (i < n4) {
        float4 v = s[i]; float4 t = d[i];
        d[i] = make_float4(t.x+v.x, t.y+v.y, t.z+v.z, t.w+v.w);
    }
}

// ---------------- COO SpMM: out[r] += val * x[c], x is a virtual concat ----------------
// 8 threads per nnz, each thread owns one float4 of the D=32 row.
__global__ void k_spmm(const int* __restrict__ rows, const int* __restrict__ cols,
                       const float* __restrict__ vals, int nnz,
                       const float* __restrict__ x0, const float* __restrict__ x1,
                       int split, float* __restrict__ out, int row_limit) {
    int t = blockIdx.x * blockDim.x + threadIdx.x;
    int e = t >> 3;
    if (e >= nnz) return;
    int r = __ldg(rows + e);
    if (r >= row_limit) return;
    int c = __ldg(cols + e);
    float v = __ldg(vals + e);
    int l4 = (t & 7) << 2;
    const float* src = (c < split) ? (x0 + ((size_t)c << 5))
                                   : (x1 + ((size_t)(c - split) << 5));
    float4 xv = *(const float4*)(src + l4);
    float* dst = out + ((size_t)r << 5) + l4;
    asm volatile("red.global.add.v4.f32 [%0], {%1, %2, %3, %4};"
                 :: "l"(dst), "f"(v*xv.x), "f"(v*xv.y), "f"(v*xv.z), "f"(v*xv.w)
                 : "memory");
}

// ---------------- dense y += A @ x  (A [n,n] row-major, x [n,32]) ----------------
// 128-row tile per block, K chunks of 64 staged in smem, split-K over gridDim.y,
// results committed with red.global.add.v4.f32 (y pre-zeroed).
#define MM_KC 64
#define MM_AS_LD 68   // pad: 16B-aligned stride, rows rg,rg+32.. land on distinct banks

__global__ void __launch_bounds__(256)
k_mm(const float* __restrict__ A, const float* __restrict__ x,
     float* __restrict__ y, int n) {
    __shared__ float As[128 * MM_AS_LD];
    __shared__ float xs[MM_KC * 32];
    int tid = threadIdx.x;
    int rg  = tid >> 3;      // 0..31   (thread's base row within tile)
    int c4  = tid & 7;       // which float4 of the 32-wide output
    int m0  = blockIdx.x * 128;

    int nchunks = (n + MM_KC - 1) / MM_KC;
    int per = (nchunks + gridDim.y - 1) / gridDim.y;
    int ci0 = blockIdx.y * per;
    int ci1 = min(nchunks, ci0 + per);

    float4 acc0 = make_float4(0,0,0,0), acc1 = acc0, acc2 = acc0, acc3 = acc0;

    for (int ci = ci0; ci < ci1; ci++) {
        int k0 = ci * MM_KC;
        int rem = n - k0;
        // stage x[k0:k0+64, :] (zero-padded)
        for (int i = tid; i < MM_KC * 8; i += 256) {
            int kk = i >> 3, cc = i & 7;
            float4 v = make_float4(0,0,0,0);
            if (kk < rem) v = *(const float4*)(x + (size_t)(k0 + kk) * 32 + cc * 4);
            *(float4*)(xs + kk * 32 + cc * 4) = v;
        }
        // stage A[m0:m0+128, k0:k0+64] (zero-padded)
        for (int i = tid; i < 128 * 16; i += 256) {
            int r = i >> 4, cc = i & 15;
            int gr = m0 + r;
            float4 v = make_float4(0,0,0,0);
            if (gr < n && cc * 4 < rem)
                v = *(const float4*)(A + (size_t)gr * n + k0 + cc * 4);
            *(float4*)(As + r * MM_AS_LD + cc * 4) = v;
        }
        __syncthreads();
        #pragma unroll 4
        for (int kk = 0; kk < MM_KC; kk += 4) {
            float4 a0 = *(const float4*)(As + (rg     ) * MM_AS_LD + kk);
            float4 a1 = *(const float4*)(As + (rg + 32) * MM_AS_LD + kk);
            float4 a2 = *(const float4*)(As + (rg + 64) * MM_AS_LD + kk);
            float4 a3 = *(const float4*)(As + (rg + 96) * MM_AS_LD + kk);
            const float* f0 = (const float*)&a0;
            const float* f1 = (const float*)&a1;
            const float* f2 = (const float*)&a2;
            const float* f3 = (const float*)&a3;
            #pragma unroll
            for (int t = 0; t < 4; t++) {
                float4 b = *(const float4*)(xs + (kk + t) * 32 + (c4 << 2));
                acc0.x = fmaf(f0[t], b.x, acc0.x); acc0.y = fmaf(f0[t], b.y, acc0.y);
                acc0.z = fmaf(f0[t], b.z, acc0.z); acc0.w = fmaf(f0[t], b.w, acc0.w);
                acc1.x = fmaf(f1[t], b.x, acc1.x); acc1.y = fmaf(f1[t], b.y, acc1.y);
                acc1.z = fmaf(f1[t], b.z, acc1.z); acc1.w = fmaf(f1[t], b.w, acc1.w);
                acc2.x = fmaf(f2[t], b.x, acc2.x); acc2.y = fmaf(f2[t], b.y, acc2.y);
                acc2.z = fmaf(f2[t], b.z, acc2.z); acc2.w = fmaf(f2[t], b.w, acc2.w);
                acc3.x = fmaf(f3[t], b.x, acc3.x); acc3.y = fmaf(f3[t], b.y, acc3.y);
                acc3.z = fmaf(f3[t], b.z, acc3.z); acc3.w = fmaf(f3[t], b.w, acc3.w);
            }
        }
        __syncthreads();
    }
    // commit (split-K partial sums via L2 reduction)
    float4 accs[4] = {acc0, acc1, acc2, acc3};
    #pragma unroll
    for (int j = 0; j < 4; j++) {
        int r = m0 + rg + 32 * j;
        if (r < n) {
            float* dst = y + (size_t)r * 32 + (c4 << 2);
            asm volatile("red.global.add.v4.f32 [%0], {%1, %2, %3, %4};"
                         :: "l"(dst), "f"(accs[j].x), "f"(accs[j].y),
                            "f"(accs[j].z), "f"(accs[j].w) : "memory");
        }
    }
}

// ---------------- group_userlayer: weighted gather-pool ----------------
__global__ void k_gul(float* __restrict__ gul, const int* __restrict__ users,
                      const float* __restrict__ mask, const float* __restrict__ accu) {
    int i = blockIdx.x * blockDim.x + threadIdx.x;
    if (i >= G_N * 32) return;
    int g = i >> 5, d = i & 31;
    float s = 0.f;
    #pragma unroll
    for (int l = 0; l < LM; l++) {
        int u = __ldg(users + g * LM + l);
        s = fmaf(__ldg(mask + g * LM + l), __ldg(accu + (size_t)u * 32 + d), s);
    }
    gul[i] = s;
}

// ---------------- gate: w = sigmoid(relu(x@W1+b1)@w2+b2), one warp per row ----------------
__global__ void k_gate(float* __restrict__ w, const float* __restrict__ gemb,
                       const float* __restrict__ gul,
                       const float* __restrict__ w1, const float* __restrict__ b1,
                       const float* __restrict__ w2, const float* __restrict__ b2) {
    int wid = (blockIdx.x * blockDim.x + threadIdx.x) >> 5;
    int lane = threadIdx.x & 31;
    if (wid >= 2 * G_N) return;
    const float* x = (wid < G_N) ? (gemb + (size_t)wid * 32)
                                 : (gul + (size_t)(wid - G_N) * 32);
    float xd = x[lane];
    float h = b1[lane];
    #pragma unroll
    for (int d = 0; d < 32; d++) {
        float a = __shfl_sync(0xffffffffu, xd, d);
        h = fmaf(a, __ldg(w1 + d * 32 + lane), h);
    }
    h = fmaxf(h, 0.f);
    float t = h * __ldg(w2 + lane);
    #pragma unroll
    for (int o = 16; o > 0; o >>= 1) t += __shfl_xor_sync(0xffffffffu, t, o);
    if (lane == 0) w[wid] = 1.f / (1.f + expf(-(t + b2[0])));
}

__global__ void k_combine(float* __restrict__ gf, const float* __restrict__ w,
                          const float* __restrict__ gemb, const float* __restrict__ gul) {
    int i = blockIdx.x * blockDim.x + threadIdx.x;
    if (i >= G_N * 32) return;
    int g = i >> 5;
    gf[i] = w[g] * gemb[i] + w[G_N + g] * gul[i];
}

// ---------------- predict MLP: one warp per sample ----------------
__global__ void k_pred(float* __restrict__ out, const int* __restrict__ gin,
                       const int* __restrict__ iin, const float* __restrict__ gf,
                       const float* __restrict__ iacc,
                       const float* __restrict__ pw1, const float* __restrict__ pb1,
                       const float* __restrict__ pw2, const float* __restrict__ pb2) {
    int wid = (blockIdx.x * blockDim.x + threadIdx.x) >> 5;
    int lane = threadIdx.x & 31;
    if (wid >= B_N) return;
    int g = __ldg(gin + wid), it = __ldg(iin + wid);
    float e = __ldg(gf + (size_t)g * 32 + lane) * __ldg(iacc + (size_t)it * 32 + lane);
    float s = 0.f;
    #pragma unroll
    for (int j = 0; j < 8; j++) {
        float p = e * __ldg(pw1 + lane * 8 + j);
        #pragma unroll
        for (int o = 16; o > 0; o >>= 1) p += __shfl_xor_sync(0xffffffffu, p, o);
        s += fmaxf(p + pb1[j], 0.f) * pw2[j];
    }
    if (lane == 0) out[wid] = 1.f / (1.f + expf(-(s + pb2[0])));
}

// ---------------- host driver ----------------
static inline int cdiv(int a, int b) { return (a + b - 1) / b; }

extern "C" void kernel_launch(void* const* d_in, const int* in_sizes, int n_in,
                              void* d_out, int out_size) {
    const int*   gin  = (const int*)  d_in[0];
    const int*   iin  = (const int*)  d_in[1];
    const float* uemb = (const float*)d_in[2];
    const float* gemb = (const float*)d_in[3];
    const float* iemb = (const float*)d_in[4];
    const int*   ui_r = (const int*)  d_in[5];
    const int*   ui_c = (const int*)  d_in[6];
    const float* ui_v = (const float*)d_in[7];
    const int*   gi_r = (const int*)  d_in[8];
    const int*   gi_c = (const int*)  d_in[9];
    const float* gi_v = (const float*)d_in[10];
    const float* ovu  = (const float*)d_in[11];
    const float* ovi  = (const float*)d_in[12];
    const int*   agu  = (const int*)  d_in[13];
    const float* agm  = (const float*)d_in[14];
    const float* gw1  = (const float*)d_in[15];
    const float* gb1  = (const float*)d_in[16];
    const float* gw2  = (const float*)d_in[17];
    const float* gb2  = (const float*)d_in[18];
    const float* pw1  = (const float*)d_in[19];
    const float* pb1  = (const float*)d_in[20];
    const float* pw2  = (const float*)d_in[21];
    const float* pb2  = (const float*)d_in[22];
    float* out = (float*)d_out;
    const int nnz_ui = in_sizes[5];
    const int nnz_gi = in_sizes[8];

    float* S = nullptr;
    cudaGetSymbolAddress((void**)&S, d_scratch);

    const int TPB = 256;
    #define F4(off)  ((float4*)(S + (off)))
    #define CF4(p)   ((const float4*)(p))

    // ======== UI graph conv: 3 layers over [U+I, 32] ========
    k_copy4<<<cdiv(80000,TPB),TPB>>>(F4(OFF_USUM), CF4(uemb), 80000);
    k_copy4<<<cdiv(64000,TPB),TPB>>>(F4(OFF_ISUM), CF4(iemb), 64000);

    int spmm_ui_grid = cdiv(nnz_ui * 8, TPB);
    int spmm_gi_grid = cdiv(nnz_gi * 8, TPB);

    // layer 1: (user_emb|item_emb) -> UI_B
    k_zero4<<<cdiv(144000,TPB),TPB>>>(F4(OFF_UI_B), 144000);
    k_spmm<<<spmm_ui_grid,TPB>>>(ui_r, ui_c, ui_v, nnz_ui, uemb, iemb, U_N,
                                 S + OFF_UI_B, U_N + I_N);
    k_axpy4<<<cdiv(80000,TPB),TPB>>>(F4(OFF_USUM), CF4(S + OFF_UI_B), 80000);
    k_axpy4<<<cdiv(64000,TPB),TPB>>>(F4(OFF_ISUM), CF4(S + OFF_UI_B + U_N*32), 64000);
    // layer 2: UI_B -> UI_A  (UI_A keeps e2 for g_layers[3])
    k_zero4<<<cdiv(144000,TPB),TPB>>>(F4(OFF_UI_A), 144000);
    k_spmm<<<spmm_ui_grid,TPB>>>(ui_r, ui_c, ui_v, nnz_ui,
                                 S + OFF_UI_B, S + OFF_UI_B + U_N*32, U_N,
                                 S + OFF_UI_A, U_N + I_N);
    k_axpy4<<<cdiv(80000,TPB),TPB>>>(F4(OFF_USUM), CF4(S + OFF_UI_A), 80000);
    k_axpy4<<<cdiv(64000,TPB),TPB>>>(F4(OFF_ISUM), CF4(S + OFF_UI_A + U_N*32), 64000);
    // layer 3: UI_A -> UI_B
    k_zero4<<<cdiv(144000,TPB),TPB>>>(F4(OFF_UI_B), 144000);
    k_spmm<<<spmm_ui_grid,TPB>>>(ui_r, ui_c, ui_v, nnz_ui,
                                 S + OFF_UI_A, S + OFF_UI_A + U_N*32, U_N,
                                 S + OFF_UI_B, U_N + I_N);
    k_axpy4<<<cdiv(80000,TPB),TPB>>>(F4(OFF_USUM), CF4(S + OFF_UI_B), 80000);
    k_axpy4<<<cdiv(64000,TPB),TPB>>>(F4(OFF_ISUM), CF4(S + OFF_UI_B + U_N*32), 64000);

    k_scale4<<<cdiv(80000,TPB),TPB>>>(F4(OFF_UM),   CF4(S + OFF_USUM), 0.25f, 80000);
    k_scale4<<<cdiv(80000,TPB),TPB>>>(F4(OFF_ACCU), CF4(S + OFF_USUM), 0.25f, 80000);
    k_scale4<<<cdiv(64000,TPB),TPB>>>(F4(OFF_IEU),  CF4(S + OFF_ISUM), 0.25f, 64000);

    // ======== GI graph conv: 3 layers over [G+I, 32] + 2 odd g_layers ========
    k_copy4<<<cdiv(64000,TPB),TPB>>>(F4(OFF_GIIS), CF4(S + OFF_IEU), 64000);
    k_copy4<<<cdiv(24000,TPB),TPB>>>(F4(OFF_GSUM), CF4(gemb), 24000);
    // layer 1: (group_emb|item_eu) -> GI_B
    k_zero4<<<cdiv(88000,TPB),TPB>>>(F4(OFF_GI_B), 88000);
    k_spmm<<<spmm_gi_grid,TPB>>>(gi_r, gi_c, gi_v, nnz_gi, gemb, S + OFF_IEU, G_N,
                                 S + OFF_GI_B, G_N + I_N);
    k_axpy4<<<cdiv(64000,TPB),TPB>>>(F4(OFF_GIIS), CF4(S + OFF_GI_B + G_N*32), 64000);
    // layer 2: GI_B -> GI_A  (group part of e2 feeds g_layers[2])
    k_zero4<<<cdiv(88000,TPB),TPB>>>(F4(OFF_GI_A), 88000);
    k_spmm<<<spmm_gi_grid,TPB>>>(gi_r, gi_c, gi_v, nnz_gi,
                                 S + OFF_GI_B, S + OFF_GI_B + G_N*32, G_N,
                                 S + OFF_GI_A, G_N + I_N);
    k_axpy4<<<cdiv(64000,TPB),TPB>>>(F4(OFF_GIIS), CF4(S + OFF_GI_A + G_N*32), 64000);
    k_axpy4<<<cdiv(24000,TPB),TPB>>>(F4(OFF_GSUM), CF4(S + OFF_GI_A), 24000);
    // layer 3: GI_A -> GI_B
    k_zero4<<<cdiv(88000,TPB),TPB>>>(F4(OFF_GI_B), 88000);
    k_spmm<<<spmm_gi_grid,TPB>>>(gi_r, gi_c, gi_v, nnz_gi,
                                 S + OFF_GI_A, S + OFF_GI_A + G_N*32, G_N,
                                 S + OFF_GI_B, G_N + I_N);
    k_axpy4<<<cdiv(64000,TPB),TPB>>>(F4(OFF_GIIS), CF4(S + OFF_GI_B + G_N*32), 64000);
    // g_layers[1]: spmm(concat(group_emb, item_emb))[:G]
    k_zero4<<<cdiv(24000,TPB),TPB>>>(F4(OFF_GSCR), 24000);
    k_spmm<<<spmm_gi_grid,TPB>>>(gi_r, gi_c, gi_v, nnz_gi, gemb, iemb, G_N,
                                 S + OFF_GSCR, G_N);
    k_axpy4<<<cdiv(24000,TPB),TPB>>>(F4(OFF_GSUM), CF4(S + OFF_GSCR), 24000);
    // g_layers[3]: spmm(concat(group_emb, item_layers[2]))[:G]   (e2 item part = UI_A[U:])
    k_zero4<<<cdiv(24000,TPB),TPB>>>(F4(OFF_GSCR), 24000);
    k_spmm<<<spmm_gi_grid,TPB>>>(gi_r, gi_c, gi_v, nnz_gi, gemb, S + OFF_UI_A + U_N*32,
                                 G_N, S + OFF_GSCR, G_N);
    k_axpy4<<<cdiv(24000,TPB),TPB>>>(F4(OFF_GSUM), CF4(S + OFF_GSCR), 24000);

    k_scale4<<<cdiv(24000,TPB),TPB>>>(F4(OFF_GEMB), CF4(S + OFF_GSUM), 0.25f, 24000);
    k_scale4<<<cdiv(64000,TPB),TPB>>>(F4(OFF_IM),   CF4(S + OFF_GIIS), 0.25f, 64000);
    k_scale4<<<cdiv(64000,TPB),TPB>>>(F4(OFF_ACCI), CF4(S + OFF_GIIS), 0.25f, 64000);

    // ======== social power series: acc = x + A@x + A@(A@x) ========
    dim3 gmmU(cdiv(U_N, 128), 8), gmmI(cdiv(I_N, 128), 8);
    // users
    k_zero4<<<cdiv(80000,TPB),TPB>>>(F4(OFF_YS), 80000);
    k_mm<<<gmmU,256>>>(ovu, S + OFF_UM, S + OFF_YS, U_N);
    k_axpy4<<<cdiv(80000,TPB),TPB>>>(F4(OFF_ACCU), CF4(S + OFF_YS), 80000);
    k_zero4<<<cdiv(80000,TPB),TPB>>>(F4(OFF_UM), 80000);
    k_mm<<<gmmU,256>>>(ovu, S + OFF_YS, S + OFF_UM, U_N);
    k_axpy4<<<cdiv(80000,TPB),TPB>>>(F4(OFF_ACCU), CF4(S + OFF_UM), 80000);
    // items
    k_zero4<<<cdiv(64000,TPB),TPB>>>(F4(OFF_YI), 64000);
    k_mm<<<gmmI,256>>>(ovi, S + OFF_IM, S + OFF_YI, I_N);
    k_axpy4<<<cdiv(64000,TPB),TPB>>>(F4(OFF_ACCI), CF4(S + OFF_YI), 64000);
    k_zero4<<<cdiv(64000,TPB),TPB>>>(F4(OFF_IM), 64000);
    k_mm<<<gmmI,256>>>(ovi, S + OFF_YI, S + OFF_IM, I_N);
    k_axpy4<<<cdiv(64000,TPB),TPB>>>(F4(OFF_ACCI), CF4(S + OFF_IM), 64000);

    // ======== pooling, gate, predict ========
    k_gul<<<cdiv(G_N*32, TPB), TPB>>>(S + OFF_GUL, agu, agm, S + OFF_ACCU);
    k_gate<<<cdiv(2*G_N*32, TPB), TPB>>>(S + OFF_W, S + OFF_GEMB, S + OFF_GUL,
                                         gw1, gb1, gw2, gb2);
    k_combine<<<cdiv(G_N*32, TPB), TPB>>>(S + OFF_GF, S + OFF_W, S + OFF_GEMB, S + OFF_GUL);
    k_pred<<<cdiv(B_N*32, TPB), TPB>>>(out, gin, iin, S + OFF_GF, S + OFF_ACCI,
                                       pw1, pb1, pw2, pb2);
    #undef F4
    #undef CF4
}

// round 4
// speedup vs baseline: 1.2590x; 1.2590x over previous
#include <cuda_runtime.h>
#include <cuda_bf16.h>
#include <cstdint>
#include <math.h>

// ---------------- problem constants ----------------
#define U_N   10000
#define G_N   3000
#define I_N   8000
#define B_N   4096
#define LM    20

// ---------------- scratch layout (floats) ----------------
constexpr int OFF_UI_A = 0;        // 576000 (holds e2 of UI conv at end)
constexpr int OFF_UI_B = 576000;   // 576000
constexpr int OFF_USUM = 1152000;  // 320000  (USUM,ISUM contiguous -> fused axpy)
constexpr int OFF_ISUM = 1472000;  // 256000
constexpr int OFF_UM   = 1728000;  // 320000  user mean (later y2 of social)
constexpr int OFF_IEU  = 2048000;  // 256000  item_emb_for_user
constexpr int OFF_GI_A = 2304000;  // 352000
constexpr int OFF_GI_B = 2656000;  // 352000
constexpr int OFF_GSUM = 3008000;  // 96000   (GSUM,GIIS contiguous -> fused axpy)
constexpr int OFF_GIIS = 3104000;  // 256000
constexpr int OFF_GSCR = 3360000;  // 96000
constexpr int OFF_GEMB = 3456000;  // 96000
constexpr int OFF_IM   = 3552000;  // 256000  i_emb (later y2 of item social)
constexpr int OFF_YS   = 3808000;  // 320000
constexpr int OFF_ACCU = 4128000;  // 320000
constexpr int OFF_YI   = 4448000;  // 256000
constexpr int OFF_ACCI = 4704000;  // 256000
constexpr int OFF_GUL  = 4960000;  // 96000
constexpr int OFF_W    = 5056000;  // 6400
constexpr int OFF_GF   = 5062400;  // 96000
constexpr int SCRATCH_TOTAL = 5158400;

__device__ float d_scratch[SCRATCH_TOTAL];

// ---------------- elementwise helpers ----------------
__global__ void k_zero4(float4* p, int n4) {
    int i = blockIdx.x * blockDim.x + threadIdx.x;
    if (i < n4) p[i] = make_float4(0.f, 0.f, 0.f, 0.f);
}
__global__ void k_copy4(float4* d, const float4* __restrict__ s, int n4) {
    int i = blockIdx.x * blockDim.x + threadIdx.x;
    if (i < n4) d[i] = s[i];
}
__global__ void k_scale4(float4* d, const float4* __restrict__ s, float a, int n4) {
    int i = blockIdx.x * blockDim.x + threadIdx.x;
    if (i < n4) { float4 v = s[i]; d[i] = make_float4(a*v.x, a*v.y, a*v.z, a*v.w); }
}
__global__ void k_scale_dup4(float4* d1, float4* d2, const float4* __restrict__ s,
                             float a, int n4) {
    int i = blockIdx.x * blockDim.x + threadIdx.x;
    if (i < n4) {
        float4 v = s[i];
        float4 r = make_float4(a*v.x, a*v.y, a*v.z, a*v.w);
        d1[i] = r; d2[i] = r;
    }
}
__global__ void k_axpy4(float4* d, const float4* __restrict__ s, int n4) {
    int i = blockIdx.x * blockDim.x + threadIdx.x;
    if (i < n4) {
        float4 v = s[i]; float4 t = d[i];
        d[i] = make_float4(t.x+v.x, t.y+v.y, t.z+v.z, t.w+v.w);
    }
}

// ---------------- COO SpMM (8 thr/nnz, red.v4) ----------------
__global__ void k_spmm(const int* __restrict__ rows, const int* __restrict__ cols,
                       const float* __restrict__ vals, int nnz,
                       const float* __restrict__ x0, const float* __restrict__ x1,
                       int split, float* __restrict__ out, int row_limit) {
    int t = blockIdx.x * blockDim.x + threadIdx.x;
    int e = t >> 3;
    if (e >= nnz) return;
    int r = __ldg(rows + e);
    if (r >= row_limit) return;
    int c = __ldg(cols + e);
    float v = __ldg(vals + e);
    int l4 = (t & 7) << 2;
    const float* src = (c < split) ? (x0 + ((size_t)c << 5))
                                   : (x1 + ((size_t)(c - split) << 5));
    float4 xv = *(const float4*)(src + l4);
    float* dst = out + ((size_t)r << 5) + l4;
    asm volatile("red.global.add.v4.f32 [%0], {%1, %2, %3, %4};"
                 :: "l"(dst), "f"(v*xv.x), "f"(v*xv.y), "f"(v*xv.z), "f"(v*xv.w)
                 : "memory");
}

// ---------------- tensor-core dense MM: y(+=)A@x, split-bf16 3-term ----------------
// A [n,n] fp32 row-major, x [n,32] fp32. M-tile 128 per block (8 warps x 16 rows),
// K chunks of 32 converted fp32 -> bf16 hi/lo in smem, mma.sync.m16n8k16.
// Commits with red.global.add.v2 into y and (optionally) y2; both pre-zeroed/init.
#define MMKC 32
#define MALD 40   // bf16 elems per padded row (80B): conflict-free ldmatrix

__device__ __forceinline__ uint32_t cvta_s(const void* p) {
    return (uint32_t)__cvta_generic_to_shared(p);
}
__device__ __forceinline__ void ldm_x4(uint32_t* r, uint32_t addr) {
    asm volatile("ldmatrix.sync.aligned.m8n8.x4.shared.b16 {%0,%1,%2,%3}, [%4];"
                 : "=r"(r[0]), "=r"(r[1]), "=r"(r[2]), "=r"(r[3]) : "r"(addr));
}
__device__ __forceinline__ void ldm_x4_t(uint32_t* r, uint32_t addr) {
    asm volatile("ldmatrix.sync.aligned.m8n8.x4.trans.shared.b16 {%0,%1,%2,%3}, [%4];"
                 : "=r"(r[0]), "=r"(r[1]), "=r"(r[2]), "=r"(r[3]) : "r"(addr));
}
__device__ __forceinline__ void mma_bf16(float* d, const uint32_t* a,
                                         uint32_t b0, uint32_t b1) {
    asm volatile("mma.sync.aligned.m16n8k16.row.col.f32.bf16.bf16.f32 "
                 "{%0,%1,%2,%3}, {%4,%5,%6,%7}, {%8,%9}, {%0,%1,%2,%3};"
                 : "+f"(d[0]), "+f"(d[1]), "+f"(d[2]), "+f"(d[3])
                 : "r"(a[0]), "r"(a[1]), "r"(a[2]), "r"(a[3]), "r"(b0), "r"(b1));
}
__device__ __forceinline__ void red2(float* p, float a, float b) {
    asm volatile("red.global.add.v2.f32 [%0], {%1, %2};"
                 :: "l"(p), "f"(a), "f"(b) : "memory");
}
__device__ __forceinline__ void cvt_split4(float4 v, __nv_bfloat16* hd, __nv_bfloat16* ld) {
    __nv_bfloat16 h0 = __float2bfloat16_rn(v.x), h1 = __float2bfloat16_rn(v.y);
    __nv_bfloat16 h2 = __float2bfloat16_rn(v.z), h3 = __float2bfloat16_rn(v.w);
    __nv_bfloat16 l0 = __float2bfloat16_rn(v.x - __bfloat162float(h0));
    __nv_bfloat16 l1 = __float2bfloat16_rn(v.y - __bfloat162float(h1));
    __nv_bfloat16 l2 = __float2bfloat16_rn(v.z - __bfloat162float(h2));
    __nv_bfloat16 l3 = __float2bfloat16_rn(v.w - __bfloat162float(h3));
    *(__nv_bfloat162*)(hd + 0) = __halves2bfloat162(h0, h1);
    *(__nv_bfloat162*)(hd + 2) = __halves2bfloat162(h2, h3);
    *(__nv_bfloat162*)(ld + 0) = __halves2bfloat162(l0, l1);
    *(__nv_bfloat162*)(ld + 2) = __halves2bfloat162(l2, l3);
}

__global__ void __launch_bounds__(256)
k_mm_tc(const float* __restrict__ A, const float* __restrict__ x,
        float* __restrict__ y, float* __restrict__ y2, int n) {
    __shared__ __nv_bfloat16 Ah[128 * MALD], Al[128 * MALD];
    __shared__ __nv_bfloat16 Xh[MMKC * MALD], Xl[MMKC * MALD];
    int tid = threadIdx.x;
    int warp = tid >> 5, lane = tid & 31;
    int m0 = blockIdx.x * 128;

    int nchunks = (n + MMKC - 1) / MMKC;
    int per = (nchunks + gridDim.y - 1) / gridDim.y;
    int ci0 = blockIdx.y * per;
    int ci1 = min(nchunks, ci0 + per);

    float acc[4][4];
    #pragma unroll
    for (int f = 0; f < 4; f++)
        #pragma unroll
        for (int j = 0; j < 4; j++) acc[f][j] = 0.f;

    // ldmatrix base addresses
    uint32_t aAddrH = cvta_s(&Ah[(warp * 16 + (lane & 15)) * MALD + ((lane >> 4) << 3)]);
    uint32_t aAddrL = cvta_s(&Al[(warp * 16 + (lane & 15)) * MALD + ((lane >> 4) << 3)]);
    uint32_t xBaseH = cvta_s(&Xh[(lane & 15) * MALD + ((lane >> 4) << 3)]);
    uint32_t xBaseL = cvta_s(&Xl[(lane & 15) * MALD + ((lane >> 4) << 3)]);

    int ar = tid >> 1, ahalf = tid & 1;     // A staging: row, 16-col half
    int xr = tid >> 3, xc = (tid & 7) * 4;  // x staging: row, col4

    for (int ci = ci0; ci < ci1; ci++) {
        int k0 = ci * MMKC;
        // ---- stage x chunk [32,32] ----
        {
            float4 v = make_float4(0.f, 0.f, 0.f, 0.f);
            if (k0 + xr < n) v = *(const float4*)(x + (size_t)(k0 + xr) * 32 + xc);
            cvt_split4(v, &Xh[xr * MALD + xc], &Xl[xr * MALD + xc]);
        }
        // ---- stage A tile [128,32] ----
        {
            int gr = m0 + ar;
            const float* Arow = A + (size_t)gr * n + k0 + ahalf * 16;
            #pragma unroll
            for (int j = 0; j < 4; j++) {
                int col = ahalf * 16 + j * 4;
                float4 v = make_float4(0.f, 0.f, 0.f, 0.f);
                if (gr < n && (k0 + col + 4) <= n) v = *(const float4*)(Arow + j * 4);
                cvt_split4(v, &Ah[ar * MALD + col], &Al[ar * MALD + col]);
            }
        }
        __syncthreads();
        // ---- compute: 2 k-steps of 16, 4 n-tiles of 8, 3 precision terms ----
        #pragma unroll
        for (int ks = 0; ks < MMKC; ks += 16) {
            uint32_t afh[4], afl[4];
            ldm_x4(afh, aAddrH + ks * 2);
            ldm_x4(afl, aAddrL + ks * 2);
            #pragma unroll
            for (int np = 0; np < 2; np++) {
                uint32_t bh[4], bl[4];
                uint32_t off = (uint32_t)(ks * MALD + np * 16) * 2;
                ldm_x4_t(bh, xBaseH + off);
                ldm_x4_t(bl, xBaseL + off);
                mma_bf16(acc[np * 2 + 0], afh, bh[0], bh[1]);
                mma_bf16(acc[np * 2 + 1], afh, bh[2], bh[3]);
                mma_bf16(acc[np * 2 + 0], afh, bl[0], bl[1]);
                mma_bf16(acc[np * 2 + 1], afh, bl[2], bl[3]);
                mma_bf16(acc[np * 2 + 0], afl, bh[0], bh[1]);
                mma_bf16(acc[np * 2 + 1], afl, bh[2], bh[3]);
            }
        }
        __syncthreads();
    }

    // ---- commit (split-K partials via L2 reduction), into y and optional y2 ----
    int gr = lane >> 2, cc = (lane & 3) * 2;
    #pragma unroll
    for (int f = 0; f < 4; f++) {
        int nc = f * 8 + cc;
        int r0 = m0 + warp * 16 + gr;
        int r1 = r0 + 8;
        if (r0 < n) {
            red2(y + (size_t)r0 * 32 + nc, acc[f][0], acc[f][1]);
            if (y2) red2(y2 + (size_t)r0 * 32 + nc, acc[f][0], acc[f][1]);
        }
        if (r1 < n) {
            red2(y + (size_t)r1 * 32 + nc, acc[f][2], acc[f][3]);
            if (y2) red2(y2 + (size_t)r1 * 32 + nc, acc[f][2], acc[f][3]);
        }
    }
}

// ---------------- group_userlayer: weighted gather-pool ----------------
__global__ void k_gul(float* __restrict__ gul, const int* __restrict__ users,
                      const float* __restrict__ mask, const float* __restrict__ accu) {
    int i = blockIdx.x * blockDim.x + threadIdx.x;
    if (i >= G_N * 32) return;
    int g = i >> 5, d = i & 31;
    float s = 0.f;
    #pragma unroll
    for (int l = 0; l < LM; l++) {
        int u = __ldg(users + g * LM + l);
        s = fmaf(__ldg(mask + g * LM + l), __ldg(accu + (size_t)u * 32 + d), s);
    }
    gul[i] = s;
}

// ---------------- gate MLP (one warp per row) ----------------
__global__ void k_gate(float* __restrict__ w, const float* __restrict__ gemb,
                       const float* __restrict__ gul,
                       const float* __restrict__ w1, const float* __restrict__ b1,
                       const float* __restrict__ w2, const float* __restrict__ b2) {
    int wid = (blockIdx.x * blockDim.x + threadIdx.x) >> 5;
    int lane = threadIdx.x & 31;
    if (wid >= 2 * G_N) return;
    const float* x = (wid < G_N) ? (gemb + (size_t)wid * 32)
                                 : (gul + (size_t)(wid - G_N) * 32);
    float xd = x[lane];
    float h = b1[lane];
    #pragma unroll
    for (int d = 0; d < 32; d++) {
        float a = __shfl_sync(0xffffffffu, xd, d);
        h = fmaf(a, __ldg(w1 + d * 32 + lane), h);
    }
    h = fmaxf(h, 0.f);
    float t = h * __ldg(w2 + lane);
    #pragma unroll
    for (int o = 16; o > 0; o >>= 1) t += __shfl_xor_sync(0xffffffffu, t, o);
    if (lane == 0) w[wid] = 1.f / (1.f + expf(-(t + b2[0])));
}

__global__ void k_combine(float* __restrict__ gf, const float* __restrict__ w,
                          const float* __restrict__ gemb, const float* __restrict__ gul) {
    int i = blockIdx.x * blockDim.x + threadIdx.x;
    if (i >= G_N * 32) return;
    int g = i >> 5;
    gf[i] = w[g] * gemb[i] + w[G_N + g] * gul[i];
}

// ---------------- predict MLP (one warp per sample) ----------------
__global__ void k_pred(float* __restrict__ out, const int* __restrict__ gin,
                       const int* __restrict__ iin, const float* __restrict__ gf,
                       const float* __restrict__ iacc,
                       const float* __restrict__ pw1, const float* __restrict__ pb1,
                       const float* __restrict__ pw2, const float* __restrict__ pb2) {
    int wid = (blockIdx.x * blockDim.x + threadIdx.x) >> 5;
    int lane = threadIdx.x & 31;
    if (wid >= B_N) return;
    int g = __ldg(gin + wid), it = __ldg(iin + wid);
    float e = __ldg(gf + (size_t)g * 32 + lane) * __ldg(iacc + (size_t)it * 32 + lane);
    float s = 0.f;
    #pragma unroll
    for (int j = 0; j < 8; j++) {
        float p = e * __ldg(pw1 + lane * 8 + j);
        #pragma unroll
        for (int o = 16; o > 0; o >>= 1) p += __shfl_xor_sync(0xffffffffu, p, o);
        s += fmaxf(p + pb1[j], 0.f) * pw2[j];
    }
    if (lane == 0) out[wid] = 1.f / (1.f + expf(-(s + pb2[0])));
}

// ---------------- host driver ----------------
static inline int cdiv(int a, int b) { return (a + b - 1) / b; }

extern "C" void kernel_launch(void* const* d_in, const int* in_sizes, int n_in,
                              void* d_out, int out_size) {
    const int*   gin  = (const int*)  d_in[0];
    const int*   iin  = (const int*)  d_in[1];
    const float* uemb = (const float*)d_in[2];
    const float* gemb = (const float*)d_in[3];
    const float* iemb = (const float*)d_in[4];
    const int*   ui_r = (const int*)  d_in[5];
    const int*   ui_c = (const int*)  d_in[6];
    const float* ui_v = (const float*)d_in[7];
    const int*   gi_r = (const int*)  d_in[8];
    const int*   gi_c = (const int*)  d_in[9];
    const float* gi_v = (const float*)d_in[10];
    const float* ovu  = (const float*)d_in[11];
    const float* ovi  = (const float*)d_in[12];
    const int*   agu  = (const int*)  d_in[13];
    const float* agm  = (const float*)d_in[14];
    const float* gw1  = (const float*)d_in[15];
    const float* gb1  = (const float*)d_in[16];
    const float* gw2  = (const float*)d_in[17];
    const float* gb2  = (const float*)d_in[18];
    const float* pw1  = (const float*)d_in[19];
    const float* pb1  = (const float*)d_in[20];
    const float* pw2  = (const float*)d_in[21];
    const float* pb2  = (const float*)d_in[22];
    float* out = (float*)d_out;
    const int nnz_ui = in_sizes[5];
    const int nnz_gi = in_sizes[8];

    float* S = nullptr;
    cudaGetSymbolAddress((void**)&S, d_scratch);

    const int TPB = 256;
    #define F4(off)  ((float4*)(S + (off)))
    #define CF4(p)   ((const float4*)(p))

    int spmm_ui_grid = cdiv(nnz_ui * 8, TPB);
    int spmm_gi_grid = cdiv(nnz_gi * 8, TPB);

    // ======== UI graph conv: 3 layers; USUM|ISUM contiguous so one axpy/layer ========
    k_copy4<<<cdiv(80000,TPB),TPB>>>(F4(OFF_USUM), CF4(uemb), 80000);
    k_copy4<<<cdiv(64000,TPB),TPB>>>(F4(OFF_ISUM), CF4(iemb), 64000);

    k_zero4<<<cdiv(144000,TPB),TPB>>>(F4(OFF_UI_B), 144000);
    k_spmm<<<spmm_ui_grid,TPB>>>(ui_r, ui_c, ui_v, nnz_ui, uemb, iemb, U_N,
                                 S + OFF_UI_B, U_N + I_N);
    k_axpy4<<<cdiv(144000,TPB),TPB>>>(F4(OFF_USUM), CF4(S + OFF_UI_B), 144000);

    k_zero4<<<cdiv(144000,TPB),TPB>>>(F4(OFF_UI_A), 144000);
    k_spmm<<<spmm_ui_grid,TPB>>>(ui_r, ui_c, ui_v, nnz_ui,
                                 S + OFF_UI_B, S + OFF_UI_B + U_N*32, U_N,
                                 S + OFF_UI_A, U_N + I_N);
    k_axpy4<<<cdiv(144000,TPB),TPB>>>(F4(OFF_USUM), CF4(S + OFF_UI_A), 144000);

    k_zero4<<<cdiv(144000,TPB),TPB>>>(F4(OFF_UI_B), 144000);
    k_spmm<<<spmm_ui_grid,TPB>>>(ui_r, ui_c, ui_v, nnz_ui,
                                 S + OFF_UI_A, S + OFF_UI_A + U_N*32, U_N,
                                 S + OFF_UI_B, U_N + I_N);
    k_axpy4<<<cdiv(144000,TPB),TPB>>>(F4(OFF_USUM), CF4(S + OFF_UI_B), 144000);

    k_scale_dup4<<<cdiv(80000,TPB),TPB>>>(F4(OFF_UM), F4(OFF_ACCU),
                                          CF4(S + OFF_USUM), 0.25f, 80000);
    k_scale4<<<cdiv(64000,TPB),TPB>>>(F4(OFF_IEU), CF4(S + OFF_ISUM), 0.25f, 64000);

    // ======== GI graph conv; GSUM|GIIS contiguous ========
    k_copy4<<<cdiv(24000,TPB),TPB>>>(F4(OFF_GSUM), CF4(gemb), 24000);
    k_copy4<<<cdiv(64000,TPB),TPB>>>(F4(OFF_GIIS), CF4(S + OFF_IEU), 64000);

    // layer 1 (item part only accumulates)
    k_zero4<<<cdiv(88000,TPB),TPB>>>(F4(OFF_GI_B), 88000);
    k_spmm<<<spmm_gi_grid,TPB>>>(gi_r, gi_c, gi_v, nnz_gi, gemb, S + OFF_IEU, G_N,
                                 S + OFF_GI_B, G_N + I_N);
    k_axpy4<<<cdiv(64000,TPB),TPB>>>(F4(OFF_GIIS), CF4(S + OFF_GI_B + G_N*32), 64000);
    // layer 2 (both group + item parts accumulate: single fused axpy)
    k_zero4<<<cdiv(88000,TPB),TPB>>>(F4(OFF_GI_A), 88000);
    k_spmm<<<spmm_gi_grid,TPB>>>(gi_r, gi_c, gi_v, nnz_gi,
                                 S + OFF_GI_B, S + OFF_GI_B + G_N*32, G_N,
                                 S + OFF_GI_A, G_N + I_N);
    k_axpy4<<<cdiv(88000,TPB),TPB>>>(F4(OFF_GSUM), CF4(S + OFF_GI_A), 88000);
    // layer 3 (item only)
    k_zero4<<<cdiv(88000,TPB),TPB>>>(F4(OFF_GI_B), 88000);
    k_spmm<<<spmm_gi_grid,TPB>>>(gi_r, gi_c, gi_v, nnz_gi,
                                 S + OFF_GI_A, S + OFF_GI_A + G_N*32, G_N,
                                 S + OFF_GI_B, G_N + I_N);
    k_axpy4<<<cdiv(64000,TPB),TPB>>>(F4(OFF_GIIS), CF4(S + OFF_GI_B + G_N*32), 64000);
    // g_layers[1]: spmm(concat(group_emb, item_emb))[:G]
    k_zero4<<<cdiv(24000,TPB),TPB>>>(F4(OFF_GSCR), 24000);
    k_spmm<<<spmm_gi_grid,TPB>>>(gi_r, gi_c, gi_v, nnz_gi, gemb, iemb, G_N,
                                 S + OFF_GSCR, G_N);
    k_axpy4<<<cdiv(24000,TPB),TPB>>>(F4(OFF_GSUM), CF4(S + OFF_GSCR), 24000);
    // g_layers[3]: spmm(concat(group_emb, item_layers[2]))[:G]  (e2 item = UI_A[U:])
    k_zero4<<<cdiv(24000,TPB),TPB>>>(F4(OFF_GSCR), 24000);
    k_spmm<<<spmm_gi_grid,TPB>>>(gi_r, gi_c, gi_v, nnz_gi, gemb, S + OFF_UI_A + U_N*32,
                                 G_N, S + OFF_GSCR, G_N);
    k_axpy4<<<cdiv(24000,TPB),TPB>>>(F4(OFF_GSUM), CF4(S + OFF_GSCR), 24000);

    k_scale4<<<cdiv(24000,TPB),TPB>>>(F4(OFF_GEMB), CF4(S + OFF_GSUM), 0.25f, 24000);
    k_scale_dup4<<<cdiv(64000,TPB),TPB>>>(F4(OFF_IM), F4(OFF_ACCI),
                                          CF4(S + OFF_GIIS), 0.25f, 64000);

    // ======== social power series on tensor cores (commit into y AND acc) ========
    dim3 gmmU(cdiv(U_N, 128), 8), gmmI(cdiv(I_N, 128), 8);
    // users: YS = A@UM (acc += YS); UM = A@YS (acc += UM)
    k_zero4<<<cdiv(80000,TPB),TPB>>>(F4(OFF_YS), 80000);
    k_mm_tc<<<gmmU,256>>>(ovu, S + OFF_UM, S + OFF_YS, S + OFF_ACCU, U_N);
    k_zero4<<<cdiv(80000,TPB),TPB>>>(F4(OFF_UM), 80000);
    k_mm_tc<<<gmmU,256>>>(ovu, S + OFF_YS, S + OFF_UM, S + OFF_ACCU, U_N);
    // items
    k_zero4<<<cdiv(64000,TPB),TPB>>>(F4(OFF_YI), 64000);
    k_mm_tc<<<gmmI,256>>>(ovi, S + OFF_IM, S + OFF_YI, S + OFF_ACCI, I_N);
    k_zero4<<<cdiv(64000,TPB),TPB>>>(F4(OFF_IM), 64000);
    k_mm_tc<<<gmmI,256>>>(ovi, S + OFF_YI, S + OFF_IM, S + OFF_ACCI, I_N);

    // ======== pooling, gate, predict ========
    k_gul<<<cdiv(G_N*32, TPB), TPB>>>(S + OFF_GUL, agu, agm, S + OFF_ACCU);
    k_gate<<<cdiv(2*G_N*32, TPB), TPB>>>(S + OFF_W, S + OFF_GEMB, S + OFF_GUL,
                                         gw1, gb1, gw2, gb2);
    k_combine<<<cdiv(G_N*32, TPB), TPB>>>(S + OFF_GF, S + OFF_W, S + OFF_GEMB, S + OFF_GUL);
    k_pred<<<cdiv(B_N*32, TPB), TPB>>>(out, gin, iin, S + OFF_GF, S + OFF_ACCI,
                                       pw1, pb1, pw2, pb2);
    #undef F4
    #undef CF4
}

// round 5
// speedup vs baseline: 1.3068x; 1.0379x over previous
#include <cuda_runtime.h>
#include <cuda_bf16.h>
#include <cstdint>
#include <math.h>

// ---------------- problem constants ----------------
#define U_N   10000
#define G_N   3000
#define I_N   8000
#define B_N   4096
#define LM    20

// ---------------- scratch layout (floats) ----------------
constexpr int OFF_UI_A = 0;        // 576000 (holds e2 of UI conv at end; UI_A|UI_B contiguous)
constexpr int OFF_UI_B = 576000;   // 576000
constexpr int OFF_USUM = 1152000;  // 320000  (USUM|ISUM contiguous: rows 0..18000)
constexpr int OFF_ISUM = 1472000;  // 256000
constexpr int OFF_UM   = 1728000;  // 320000  user mean (later y2 of social)
constexpr int OFF_IEU  = 2048000;  // 256000  item_emb_for_user
constexpr int OFF_GI_A = 2304000;  // 352000  (GI_A|GI_B contiguous)
constexpr int OFF_GI_B = 2656000;  // 352000
constexpr int OFF_GSUM = 3008000;  // 96000   (GSUM|GIIS contiguous: rows 0..11000)
constexpr int OFF_GIIS = 3104000;  // 256000
constexpr int OFF_GEMB = 3456000;  // 96000
constexpr int OFF_IM   = 3552000;  // 256000  i_emb (later y2 of item social)
constexpr int OFF_YS   = 3808000;  // 320000
constexpr int OFF_ACCU = 4128000;  // 320000
constexpr int OFF_YI   = 4448000;  // 256000
constexpr int OFF_ACCI = 4704000;  // 256000
constexpr int OFF_GUL  = 4960000;  // 96000
constexpr int OFF_W    = 5056000;  // 6400
constexpr int OFF_GF   = 5062400;  // 96000
constexpr int SCRATCH_TOTAL = 5158400;

__device__ float d_scratch[SCRATCH_TOTAL];

// ---------------- elementwise helpers ----------------
__global__ void k_zero4(float4* p, int n4) {
    int i = blockIdx.x * blockDim.x + threadIdx.x;
    if (i < n4) p[i] = make_float4(0.f, 0.f, 0.f, 0.f);
}
__global__ void k_zero2buf(float4* p1, int n1, float4* p2, int n2) {
    int i = blockIdx.x * blockDim.x + threadIdx.x;
    if (i < n1) p1[i] = make_float4(0.f, 0.f, 0.f, 0.f);
    else if (i < n1 + n2) p2[i - n1] = make_float4(0.f, 0.f, 0.f, 0.f);
}
__global__ void k_copy2(float4* d1, const float4* __restrict__ s1, int n1,
                        float4* d2, const float4* __restrict__ s2, int n2) {
    int i = blockIdx.x * blockDim.x + threadIdx.x;
    if (i < n1) d1[i] = s1[i];
    else if (i < n1 + n2) d2[i - n1] = s2[i - n1];
}
__global__ void k_copy4(float4* d, const float4* __restrict__ s, int n4) {
    int i = blockIdx.x * blockDim.x + threadIdx.x;
    if (i < n4) d[i] = s[i];
}
__global__ void k_scale4(float4* d, const float4* __restrict__ s, float a, int n4) {
    int i = blockIdx.x * blockDim.x + threadIdx.x;
    if (i < n4) { float4 v = s[i]; d[i] = make_float4(a*v.x, a*v.y, a*v.z, a*v.w); }
}
__global__ void k_scale_dup4(float4* d1, float4* d2, const float4* __restrict__ s,
                             float a, int n4) {
    int i = blockIdx.x * blockDim.x + threadIdx.x;
    if (i < n4) {
        float4 v = s[i];
        float4 r = make_float4(a*v.x, a*v.y, a*v.z, a*v.w);
        d1[i] = r; d2[i] = r;
    }
}

// ---------------- COO SpMM with fused sum accumulation ----------------
// out[r] += v*x[c] (always). If sum != null and r >= sum_lo: sum[r] += v*x[c] too.
__global__ void k_spmm(const int* __restrict__ rows, const int* __restrict__ cols,
                       const float* __restrict__ vals, int nnz,
                       const float* __restrict__ x0, const float* __restrict__ x1,
                       int split, float* __restrict__ out, int row_limit,
                       float* __restrict__ sum, int sum_lo) {
    int t = blockIdx.x * blockDim.x + threadIdx.x;
    int e = t >> 3;
    if (e >= nnz) return;
    int r = __ldg(rows + e);
    if (r >= row_limit) return;
    int c = __ldg(cols + e);
    float v = __ldg(vals + e);
    int l4 = (t & 7) << 2;
    const float* src = (c < split) ? (x0 + ((size_t)c << 5))
                                   : (x1 + ((size_t)(c - split) << 5));
    float4 xv = *(const float4*)(src + l4);
    float a = v*xv.x, b = v*xv.y, cc = v*xv.z, d = v*xv.w;
    size_t ro = ((size_t)r << 5) + l4;
    asm volatile("red.global.add.v4.f32 [%0], {%1, %2, %3, %4};"
                 :: "l"(out + ro), "f"(a), "f"(b), "f"(cc), "f"(d) : "memory");
    if (sum != nullptr && r >= sum_lo)
        asm volatile("red.global.add.v4.f32 [%0], {%1, %2, %3, %4};"
                     :: "l"(sum + ro), "f"(a), "f"(b), "f"(cc), "f"(d) : "memory");
}

// ---------------- tensor-core dense MM: y(+=)A@x, split-bf16 3-term ----------------
// A [n,n] fp32 row-major, x [n,32] fp32. 128-row tile (8 warps x 16 rows),
// K chunks of 32, software-pipelined register prefetch of next chunk,
// truncation-based fp32 -> bf16 hi/lo split, mma.sync.m16n8k16.
// Commits via red.global.add.v2 into y and optional y2 (both pre-zeroed/init).
#define MMKC 32
#define MALD 40   // bf16 elems per padded smem row (80B)

__device__ __forceinline__ uint32_t cvta_s(const void* p) {
    return (uint32_t)__cvta_generic_to_shared(p);
}
__device__ __forceinline__ void ldm_x4(uint32_t* r, uint32_t addr) {
    asm volatile("ldmatrix.sync.aligned.m8n8.x4.shared.b16 {%0,%1,%2,%3}, [%4];"
                 : "=r"(r[0]), "=r"(r[1]), "=r"(r[2]), "=r"(r[3]) : "r"(addr));
}
__device__ __forceinline__ void ldm_x4_t(uint32_t* r, uint32_t addr) {
    asm volatile("ldmatrix.sync.aligned.m8n8.x4.trans.shared.b16 {%0,%1,%2,%3}, [%4];"
                 : "=r"(r[0]), "=r"(r[1]), "=r"(r[2]), "=r"(r[3]) : "r"(addr));
}
__device__ __forceinline__ void mma_bf16(float* d, const uint32_t* a,
                                         uint32_t b0, uint32_t b1) {
    asm volatile("mma.sync.aligned.m16n8k16.row.col.f32.bf16.bf16.f32 "
                 "{%0,%1,%2,%3}, {%4,%5,%6,%7}, {%8,%9}, {%0,%1,%2,%3};"
                 : "+f"(d[0]), "+f"(d[1]), "+f"(d[2]), "+f"(d[3])
                 : "r"(a[0]), "r"(a[1]), "r"(a[2]), "r"(a[3]), "r"(b0), "r"(b1));
}
__device__ __forceinline__ void red2(float* p, float a, float b) {
    asm volatile("red.global.add.v2.f32 [%0], {%1, %2};"
                 :: "l"(p), "f"(a), "f"(b) : "memory");
}
// truncation split: hi = top 16 bits (PRMT pack), lo = x - hi (then truncated too)
__device__ __forceinline__ void st_split4(float4 v, __nv_bfloat16* hd, __nv_bfloat16* ldst) {
    uint32_t x0 = __float_as_uint(v.x), x1 = __float_as_uint(v.y);
    uint32_t x2 = __float_as_uint(v.z), x3 = __float_as_uint(v.w);
    uint32_t h01, h23;
    asm("prmt.b32 %0, %1, %2, 0x7632;" : "=r"(h01) : "r"(x0), "r"(x1));
    asm("prmt.b32 %0, %1, %2, 0x7632;" : "=r"(h23) : "r"(x2), "r"(x3));
    float l0 = v.x - __uint_as_float(x0 & 0xFFFF0000u);
    float l1 = v.y - __uint_as_float(x1 & 0xFFFF0000u);
    float l2 = v.z - __uint_as_float(x2 & 0xFFFF0000u);
    float l3 = v.w - __uint_as_float(x3 & 0xFFFF0000u);
    uint32_t lo01, lo23;
    asm("prmt.b32 %0, %1, %2, 0x7632;" : "=r"(lo01)
        : "r"(__float_as_uint(l0)), "r"(__float_as_uint(l1)));
    asm("prmt.b32 %0, %1, %2, 0x7632;" : "=r"(lo23)
        : "r"(__float_as_uint(l2)), "r"(__float_as_uint(l3)));
    *(uint2*)hd   = make_uint2(h01, h23);
    *(uint2*)ldst = make_uint2(lo01, lo23);
}

__global__ void __launch_bounds__(256, 2)
k_mm_tc(const float* __restrict__ A, const float* __restrict__ x,
        float* __restrict__ y, float* __restrict__ y2, int n) {
    __shared__ __nv_bfloat16 Ah[128 * MALD], Al[128 * MALD];
    __shared__ __nv_bfloat16 Xh[MMKC * MALD], Xl[MMKC * MALD];
    int tid = threadIdx.x;
    int warp = tid >> 5, lane = tid & 31;
    int m0 = blockIdx.x * 128;

    int nchunks = (n + MMKC - 1) / MMKC;
    int per = (nchunks + gridDim.y - 1) / gridDim.y;
    int ci0 = blockIdx.y * per;
    int ci1 = min(nchunks, ci0 + per);

    float acc[4][4];
    #pragma unroll
    for (int f = 0; f < 4; f++)
        #pragma unroll
        for (int j = 0; j < 4; j++) acc[f][j] = 0.f;

    uint32_t aAddrH = cvta_s(&Ah[(warp * 16 + (lane & 15)) * MALD + ((lane >> 4) << 3)]);
    uint32_t aAddrL = cvta_s(&Al[(warp * 16 + (lane & 15)) * MALD + ((lane >> 4) << 3)]);
    uint32_t xBaseH = cvta_s(&Xh[(lane & 15) * MALD + ((lane >> 4) << 3)]);
    uint32_t xBaseL = cvta_s(&Xl[(lane & 15) * MALD + ((lane >> 4) << 3)]);

    int ar = tid >> 1, ahalf = tid & 1;     // A staging: row, 16-col half
    int xr = tid >> 3, xc = (tid & 7) << 2; // x staging: row, col4
    int gr = m0 + ar;
    const float* Arow = A + (size_t)gr * n + ahalf * 16;

    float4 aR[4], xR;
    const float4 Z4 = make_float4(0.f, 0.f, 0.f, 0.f);
    // prologue: load first chunk into registers
    {
        int k0 = ci0 * MMKC;
        xR = Z4;
        if (k0 + xr < n) xR = *(const float4*)(x + (size_t)(k0 + xr) * 32 + xc);
        #pragma unroll
        for (int j = 0; j < 4; j++) {
            int col = ahalf * 16 + j * 4;
            aR[j] = Z4;
            if (gr < n && (k0 + col + 4) <= n) aR[j] = *(const float4*)(Arow + k0 + j * 4);
        }
    }

    for (int ci = ci0; ci < ci1; ci++) {
        // ---- convert current registers -> smem (hi/lo split) ----
        st_split4(xR, &Xh[xr * MALD + xc], &Xl[xr * MALD + xc]);
        #pragma unroll
        for (int j = 0; j < 4; j++) {
            int col = ahalf * 16 + j * 4;
            st_split4(aR[j], &Ah[ar * MALD + col], &Al[ar * MALD + col]);
        }
        __syncthreads();
        // ---- issue next chunk's loads (latency hidden under MMA below) ----
        if (ci + 1 < ci1) {
            int k0 = (ci + 1) * MMKC;
            xR = Z4;
            if (k0 + xr < n) xR = *(const float4*)(x + (size_t)(k0 + xr) * 32 + xc);
            #pragma unroll
            for (int j = 0; j < 4; j++) {
                int col = ahalf * 16 + j * 4;
                aR[j] = Z4;
                if (gr < n && (k0 + col + 4) <= n) aR[j] = *(const float4*)(Arow + k0 + j * 4);
            }
        }
        // ---- MMA: 2 k-steps of 16, 2 n-halves, 3 precision terms ----
        #pragma unroll
        for (int ks = 0; ks < MMKC; ks += 16) {
            uint32_t afh[4], afl[4];
            ldm_x4(afh, aAddrH + ks * 2);
            ldm_x4(afl, aAddrL + ks * 2);
            #pragma unroll
            for (int np = 0; np < 2; np++) {
                uint32_t bh[4], bl[4];
                uint32_t off = (uint32_t)(ks * MALD + np * 16) * 2;
                ldm_x4_t(bh, xBaseH + off);
                ldm_x4_t(bl, xBaseL + off);
                mma_bf16(acc[np * 2 + 0], afh, bh[0], bh[1]);
                mma_bf16(acc[np * 2 + 1], afh, bh[2], bh[3]);
                mma_bf16(acc[np * 2 + 0], afh, bl[0], bl[1]);
                mma_bf16(acc[np * 2 + 1], afh, bl[2], bl[3]);
                mma_bf16(acc[np * 2 + 0], afl, bh[0], bh[1]);
                mma_bf16(acc[np * 2 + 1], afl, bh[2], bh[3]);
            }
        }
        __syncthreads();
    }

    // ---- commit (split-K partials via L2 reduction), into y and optional y2 ----
    int gr8 = lane >> 2, cc = (lane & 3) * 2;
    #pragma unroll
    for (int f = 0; f < 4; f++) {
        int nc = f * 8 + cc;
        int r0 = m0 + warp * 16 + gr8;
        int r1 = r0 + 8;
        if (r0 < n) {
            red2(y + (size_t)r0 * 32 + nc, acc[f][0], acc[f][1]);
            if (y2) red2(y2 + (size_t)r0 * 32 + nc, acc[f][0], acc[f][1]);
        }
        if (r1 < n) {
            red2(y + (size_t)r1 * 32 + nc, acc[f][2], acc[f][3]);
            if (y2) red2(y2 + (size_t)r1 * 32 + nc, acc[f][2], acc[f][3]);
        }
    }
}

// ---------------- group_userlayer: weighted gather-pool ----------------
__global__ void k_gul(float* __restrict__ gul, const int* __restrict__ users,
                      const float* __restrict__ mask, const float* __restrict__ accu) {
    int i = blockIdx.x * blockDim.x + threadIdx.x;
    if (i >= G_N * 32) return;
    int g = i >> 5, d = i & 31;
    float s = 0.f;
    #pragma unroll
    for (int l = 0; l < LM; l++) {
        int u = __ldg(users + g * LM + l);
        s = fmaf(__ldg(mask + g * LM + l), __ldg(accu + (size_t)u * 32 + d), s);
    }
    gul[i] = s;
}

// ---------------- gate MLP (one warp per row) ----------------
__global__ void k_gate(float* __restrict__ w, const float* __restrict__ gemb,
                       const float* __restrict__ gul,
                       const float* __restrict__ w1, const float* __restrict__ b1,
                       const float* __restrict__ w2, const float* __restrict__ b2) {
    int wid = (blockIdx.x * blockDim.x + threadIdx.x) >> 5;
    int lane = threadIdx.x & 31;
    if (wid >= 2 * G_N) return;
    const float* x = (wid < G_N) ? (gemb + (size_t)wid * 32)
                                 : (gul + (size_t)(wid - G_N) * 32);
    float xd = x[lane];
    float h = b1[lane];
    #pragma unroll
    for (int d = 0; d < 32; d++) {
        float a = __shfl_sync(0xffffffffu, xd, d);
        h = fmaf(a, __ldg(w1 + d * 32 + lane), h);
    }
    h = fmaxf(h, 0.f);
    float t = h * __ldg(w2 + lane);
    #pragma unroll
    for (int o = 16; o > 0; o >>= 1) t += __shfl_xor_sync(0xffffffffu, t, o);
    if (lane == 0) w[wid] = 1.f / (1.f + expf(-(t + b2[0])));
}

__global__ void k_combine(float* __restrict__ gf, const float* __restrict__ w,
                          const float* __restrict__ gemb, const float* __restrict__ gul) {
    int i = blockIdx.x * blockDim.x + threadIdx.x;
    if (i >= G_N * 32) return;
    int g = i >> 5;
    gf[i] = w[g] * gemb[i] + w[G_N + g] * gul[i];
}

// ---------------- predict MLP (one warp per sample) ----------------
__global__ void k_pred(float* __restrict__ out, const int* __restrict__ gin,
                       const int* __restrict__ iin, const float* __restrict__ gf,
                       const float* __restrict__ iacc,
                       const float* __restrict__ pw1, const float* __restrict__ pb1,
                       const float* __restrict__ pw2, const float* __restrict__ pb2) {
    int wid = (blockIdx.x * blockDim.x + threadIdx.x) >> 5;
    int lane = threadIdx.x & 31;
    if (wid >= B_N) return;
    int g = __ldg(gin + wid), it = __ldg(iin + wid);
    float e = __ldg(gf + (size_t)g * 32 + lane) * __ldg(iacc + (size_t)it * 32 + lane);
    float s = 0.f;
    #pragma unroll
    for (int j = 0; j < 8; j++) {
        float p = e * __ldg(pw1 + lane * 8 + j);
        #pragma unroll
        for (int o = 16; o > 0; o >>= 1) p += __shfl_xor_sync(0xffffffffu, p, o);
        s += fmaxf(p + pb1[j], 0.f) * pw2[j];
    }
    if (lane == 0) out[wid] = 1.f / (1.f + expf(-(s + pb2[0])));
}

// ---------------- host driver ----------------
static inline int cdiv(int a, int b) { return (a + b - 1) / b; }

extern "C" void kernel_launch(void* const* d_in, const int* in_sizes, int n_in,
                              void* d_out, int out_size) {
    const int*   gin  = (const int*)  d_in[0];
    const int*   iin  = (const int*)  d_in[1];
    const float* uemb = (const float*)d_in[2];
    const float* gemb = (const float*)d_in[3];
    const float* iemb = (const float*)d_in[4];
    const int*   ui_r = (const int*)  d_in[5];
    const int*   ui_c = (const int*)  d_in[6];
    const float* ui_v = (const float*)d_in[7];
    const int*   gi_r = (const int*)  d_in[8];
    const int*   gi_c = (const int*)  d_in[9];
    const float* gi_v = (const float*)d_in[10];
    const float* ovu  = (const float*)d_in[11];
    const float* ovi  = (const float*)d_in[12];
    const int*   agu  = (const int*)  d_in[13];
    const float* agm  = (const float*)d_in[14];
    const float* gw1  = (const float*)d_in[15];
    const float* gb1  = (const float*)d_in[16];
    const float* gw2  = (const float*)d_in[17];
    const float* gb2  = (const float*)d_in[18];
    const float* pw1  = (const float*)d_in[19];
    const float* pb1  = (const float*)d_in[20];
    const float* pw2  = (const float*)d_in[21];
    const float* pb2  = (const float*)d_in[22];
    float* out = (float*)d_out;
    const int nnz_ui = in_sizes[5];
    const int nnz_gi = in_sizes[8];

    float* S = nullptr;
    cudaGetSymbolAddress((void**)&S, d_scratch);

    const int TPB = 256;
    #define F4(off)  ((float4*)(S + (off)))
    #define CF4(p)   ((const float4*)(p))

    int spmm_ui_grid = cdiv(nnz_ui * 8, TPB);
    int spmm_gi_grid = cdiv(nnz_gi * 8, TPB);

    // ======== UI graph conv: 3 layers, sums fused into spmm ========
    k_copy2<<<cdiv(144000,TPB),TPB>>>(F4(OFF_USUM), CF4(uemb), 80000,
                                      F4(OFF_ISUM), CF4(iemb), 64000);
    // zero both ping-pong buffers (contiguous)
    k_zero4<<<cdiv(288000,TPB),TPB>>>(F4(OFF_UI_A), 288000);
    // l1 -> UI_B, l2 -> UI_A (kept: e2 item part feeds g_layers[3]), l3 -> UI_B
    k_spmm<<<spmm_ui_grid,TPB>>>(ui_r, ui_c, ui_v, nnz_ui, uemb, iemb, U_N,
                                 S + OFF_UI_B, U_N + I_N, S + OFF_USUM, 0);
    k_spmm<<<spmm_ui_grid,TPB>>>(ui_r, ui_c, ui_v, nnz_ui,
                                 S + OFF_UI_B, S + OFF_UI_B + U_N*32, U_N,
                                 S + OFF_UI_A, U_N + I_N, S + OFF_USUM, 0);
    k_zero4<<<cdiv(144000,TPB),TPB>>>(F4(OFF_UI_B), 144000);
    k_spmm<<<spmm_ui_grid,TPB>>>(ui_r, ui_c, ui_v, nnz_ui,
                                 S + OFF_UI_A, S + OFF_UI_A + U_N*32, U_N,
                                 S + OFF_UI_B, U_N + I_N, S + OFF_USUM, 0);

    k_scale_dup4<<<cdiv(80000,TPB),TPB>>>(F4(OFF_UM), F4(OFF_ACCU),
                                          CF4(S + OFF_USUM), 0.25f, 80000);
    // IEU = 0.25*ISUM, and GIIS initialized to the same value
    k_scale_dup4<<<cdiv(64000,TPB),TPB>>>(F4(OFF_IEU), F4(OFF_GIIS),
                                          CF4(S + OFF_ISUM), 0.25f, 64000);
    k_copy4<<<cdiv(24000,TPB),TPB>>>(F4(OFF_GSUM), CF4(gemb), 24000);

    // ======== GI graph conv (sums fused; GSUM|GIIS is rows 0..11000) ========
    k_zero4<<<cdiv(176000,TPB),TPB>>>(F4(OFF_GI_A), 176000);
    // l1 -> GI_B (only item rows accumulate)
    k_spmm<<<spmm_gi_grid,TPB>>>(gi_r, gi_c, gi_v, nnz_gi, gemb, S + OFF_IEU, G_N,
                                 S + OFF_GI_B, G_N + I_N, S + OFF_GSUM, G_N);
    // l2 -> GI_A (all rows accumulate)
    k_spmm<<<spmm_gi_grid,TPB>>>(gi_r, gi_c, gi_v, nnz_gi,
                                 S + OFF_GI_B, S + OFF_GI_B + G_N*32, G_N,
                                 S + OFF_GI_A, G_N + I_N, S + OFF_GSUM, 0);
    k_zero4<<<cdiv(88000,TPB),TPB>>>(F4(OFF_GI_B), 88000);
    // l3 -> GI_B (item rows only)
    k_spmm<<<spmm_gi_grid,TPB>>>(gi_r, gi_c, gi_v, nnz_gi,
                                 S + OFF_GI_A, S + OFF_GI_A + G_N*32, G_N,
                                 S + OFF_GI_B, G_N + I_N, S + OFF_GSUM, G_N);
    // g_layers[1]: spmm(concat(group_emb, item_emb))[:G] accumulated straight into GSUM
    k_spmm<<<spmm_gi_grid,TPB>>>(gi_r, gi_c, gi_v, nnz_gi, gemb, iemb, G_N,
                                 S + OFF_GSUM, G_N, nullptr, 0);
    // g_layers[3]: spmm(concat(group_emb, item_layers[2]))[:G]  (e2 item = UI_A[U:])
    k_spmm<<<spmm_gi_grid,TPB>>>(gi_r, gi_c, gi_v, nnz_gi, gemb, S + OFF_UI_A + U_N*32,
                                 G_N, S + OFF_GSUM, G_N, nullptr, 0);

    k_scale4<<<cdiv(24000,TPB),TPB>>>(F4(OFF_GEMB), CF4(S + OFF_GSUM), 0.25f, 24000);
    k_scale_dup4<<<cdiv(64000,TPB),TPB>>>(F4(OFF_IM), F4(OFF_ACCI),
                                          CF4(S + OFF_GIIS), 0.25f, 64000);

    // ======== social power series on tensor cores (commit into y AND acc) ========
    dim3 gmmU(cdiv(U_N, 128), 8), gmmI(cdiv(I_N, 128), 8);
    k_zero2buf<<<cdiv(144000,TPB),TPB>>>(F4(OFF_YS), 80000, F4(OFF_YI), 64000);
    k_mm_tc<<<gmmU,256>>>(ovu, S + OFF_UM, S + OFF_YS, S + OFF_ACCU, U_N);
    k_mm_tc<<<gmmI,256>>>(ovi, S + OFF_IM, S + OFF_YI, S + OFF_ACCI, I_N);
    k_zero2buf<<<cdiv(144000,TPB),TPB>>>(F4(OFF_UM), 80000, F4(OFF_IM), 64000);
    k_mm_tc<<<gmmU,256>>>(ovu, S + OFF_YS, S + OFF_UM, S + OFF_ACCU, U_N);
    k_mm_tc<<<gmmI,256>>>(ovi, S + OFF_YI, S + OFF_IM, S + OFF_ACCI, I_N);

    // ======== pooling, gate, predict ========
    k_gul<<<cdiv(G_N*32, TPB), TPB>>>(S + OFF_GUL, agu, agm, S + OFF_ACCU);
    k_gate<<<cdiv(2*G_N*32, TPB), TPB>>>(S + OFF_W, S + OFF_GEMB, S + OFF_GUL,
                                         gw1, gb1, gw2, gb2);
    k_combine<<<cdiv(G_N*32, TPB), TPB>>>(S + OFF_GF, S + OFF_W, S + OFF_GEMB, S + OFF_GUL);
    k_pred<<<cdiv(B_N*32, TPB), TPB>>>(out, gin, iin, S + OFF_GF, S + OFF_ACCI,
                                       pw1, pb1, pw2, pb2);
    #undef F4
    #undef CF4
}

// round 7
// speedup vs baseline: 1.4019x; 1.0728x over previous
#include <cuda_runtime.h>
#include <cuda_bf16.h>
#include <cstdint>
#include <math.h>

// ---------------- problem constants ----------------
#define U_N   10000
#define G_N   3000
#define I_N   8000
#define B_N   4096
#define LM    20

// ---------------- scratch layout (floats) ----------------
constexpr int OFF_UI_A = 0;        // 576000 (UI_A|UI_B contiguous; A holds e2 at end)
constexpr int OFF_UI_B = 576000;   // 576000
constexpr int OFF_USUM = 1152000;  // 320000  (USUM|ISUM contiguous: rows 0..18000)
constexpr int OFF_ISUM = 1472000;  // 256000
constexpr int OFF_UM   = 1728000;  // 320000  user social term 2 (A@A@USUM)
constexpr int OFF_IEU  = 2048000;  // 256000  item_emb_for_user (0.25*ISUM)
constexpr int OFF_GI_A = 2304000;  // 352000  (GI_A|GI_B contiguous)
constexpr int OFF_GI_B = 2656000;  // 352000
constexpr int OFF_GSUM = 3008000;  // 96000   (GSUM|GIIS contiguous: rows 0..11000)
constexpr int OFF_GIIS = 3104000;  // 256000
constexpr int OFF_IM   = 3552000;  // 256000  item social term 2  (IM|YS contiguous)
constexpr int OFF_YS   = 3808000;  // 320000  user social term 1 (A@USUM)
constexpr int OFF_YI   = 4448000;  // 256000  item social term 1
constexpr int OFF_GUL  = 4960000;  // 96000
constexpr int OFF_W    = 5056000;  // 6400
constexpr int OFF_GF   = 5062400;  // 96000
constexpr int SCRATCH_TOTAL = 5158400;

__device__ float d_scratch[SCRATCH_TOTAL];

// ---------------- elementwise helpers ----------------
__global__ void k_zero4(float4* p, int n4) {
    int i = blockIdx.x * blockDim.x + threadIdx.x;
    if (i < n4) p[i] = make_float4(0.f, 0.f, 0.f, 0.f);
}
__global__ void k_zero2buf(float4* p1, int n1, float4* p2, int n2) {
    int i = blockIdx.x * blockDim.x + threadIdx.x;
    if (i < n1) p1[i] = make_float4(0.f, 0.f, 0.f, 0.f);
    else if (i < n1 + n2) p2[i - n1] = make_float4(0.f, 0.f, 0.f, 0.f);
}
__global__ void k_copy2(float4* d1, const float4* __restrict__ s1, int n1,
                        float4* d2, const float4* __restrict__ s2, int n2) {
    int i = blockIdx.x * blockDim.x + threadIdx.x;
    if (i < n1) d1[i] = s1[i];
    else if (i < n1 + n2) d2[i - n1] = s2[i - n1];
}
__global__ void k_copy4(float4* d, const float4* __restrict__ s, int n4) {
    int i = blockIdx.x * blockDim.x + threadIdx.x;
    if (i < n4) d[i] = s[i];
}
__global__ void k_scale_dup4(float4* d1, float4* d2, const float4* __restrict__ s,
                             float a, int n4) {
    int i = blockIdx.x * blockDim.x + threadIdx.x;
    if (i < n4) {
        float4 v = s[i];
        float4 r = make_float4(a*v.x, a*v.y, a*v.z, a*v.w);
        d1[i] = r; d2[i] = r;
    }
}

// ---------------- COO SpMM, warp-cooperative index loads ----------------
// Each warp handles 4 edges: lanes 0-11 load the 12 r/c/v scalars, shfl-broadcast.
// out[r] += v*x[c]; if sum && r >= sum_lo: sum[r] += v*x[c].
__global__ void k_spmm(const int* __restrict__ rows, const int* __restrict__ cols,
                       const float* __restrict__ vals, int nnz,
                       const float* __restrict__ x0, const float* __restrict__ x1,
                       int split, float* __restrict__ out, int row_limit,
                       float* __restrict__ sum, int sum_lo) {
    int gw = (blockIdx.x * blockDim.x + threadIdx.x) >> 5;
    int lane = threadIdx.x & 31;
    int e0 = gw << 2;
    if (e0 >= nnz) return;
    int ld = 0;
    int which = lane >> 2;              // 0:rows 1:cols 2:vals
    int j4 = e0 + (lane & 3);
    if (j4 < nnz) {
        if (which == 0)      ld = __ldg(rows + j4);
        else if (which == 1) ld = __ldg(cols + j4);
        else if (which == 2) ld = __float_as_int(__ldg(vals + j4));
    }
    int sub = lane >> 3;                // which of the 4 edges
    int l4  = (lane & 7) << 2;          // float4 slot within row
    int e = e0 + sub;
    int r =                 __shfl_sync(0xffffffffu, ld, sub);
    int c =                 __shfl_sync(0xffffffffu, ld, 4 + sub);
    float v = __int_as_float(__shfl_sync(0xffffffffu, ld, 8 + sub));
    if (e >= nnz || r >= row_limit) return;
    const float* src = (c < split) ? (x0 + ((size_t)c << 5))
                                   : (x1 + ((size_t)(c - split) << 5));
    float4 xv = *(const float4*)(src + l4);
    float a = v*xv.x, b = v*xv.y, cc = v*xv.z, d = v*xv.w;
    size_t ro = ((size_t)r << 5) + l4;
    asm volatile("red.global.add.v4.f32 [%0], {%1, %2, %3, %4};"
                 :: "l"(out + ro), "f"(a), "f"(b), "f"(cc), "f"(d) : "memory");
    if (sum != nullptr && r >= sum_lo)
        asm volatile("red.global.add.v4.f32 [%0], {%1, %2, %3, %4};"
                     :: "l"(sum + ro), "f"(a), "f"(b), "f"(cc), "f"(d) : "memory");
}

// ---------------- tensor-core dense MM, two fused problems ----------------
// Blocks with blockIdx.x < gx0 run problem 0 (A0@x0 -> y0), rest run problem 1.
// 128-row tile, K chunks of 32, register-prefetch pipeline, split-bf16 3-term,
// mma.sync.m16n8k16, split-K over gridDim.y committed via red.global.add.v2.
#define MMKC 32
#define MALD 40

__device__ __forceinline__ uint32_t cvta_s(const void* p) {
    return (uint32_t)__cvta_generic_to_shared(p);
}
__device__ __forceinline__ void ldm_x4(uint32_t* r, uint32_t addr) {
    asm volatile("ldmatrix.sync.aligned.m8n8.x4.shared.b16 {%0,%1,%2,%3}, [%4];"
                 : "=r"(r[0]), "=r"(r[1]), "=r"(r[2]), "=r"(r[3]) : "r"(addr));
}
__device__ __forceinline__ void ldm_x4_t(uint32_t* r, uint32_t addr) {
    asm volatile("ldmatrix.sync.aligned.m8n8.x4.trans.shared.b16 {%0,%1,%2,%3}, [%4];"
                 : "=r"(r[0]), "=r"(r[1]), "=r"(r[2]), "=r"(r[3]) : "r"(addr));
}
__device__ __forceinline__ void mma_bf16(float* d, const uint32_t* a,
                                         uint32_t b0, uint32_t b1) {
    asm volatile("mma.sync.aligned.m16n8k16.row.col.f32.bf16.bf16.f32 "
                 "{%0,%1,%2,%3}, {%4,%5,%6,%7}, {%8,%9}, {%0,%1,%2,%3};"
                 : "+f"(d[0]), "+f"(d[1]), "+f"(d[2]), "+f"(d[3])
                 : "r"(a[0]), "r"(a[1]), "r"(a[2]), "r"(a[3]), "r"(b0), "r"(b1));
}
__device__ __forceinline__ void red2(float* p, float a, float b) {
    asm volatile("red.global.add.v2.f32 [%0], {%1, %2};"
                 :: "l"(p), "f"(a), "f"(b) : "memory");
}
__device__ __forceinline__ void st_split4(float4 v, __nv_bfloat16* hd, __nv_bfloat16* ldst) {
    uint32_t x0 = __float_as_uint(v.x), x1 = __float_as_uint(v.y);
    uint32_t x2 = __float_as_uint(v.z), x3 = __float_as_uint(v.w);
    uint32_t h01, h23;
    asm("prmt.b32 %0, %1, %2, 0x7632;" : "=r"(h01) : "r"(x0), "r"(x1));
    asm("prmt.b32 %0, %1, %2, 0x7632;" : "=r"(h23) : "r"(x2), "r"(x3));
    float l0 = v.x - __uint_as_float(x0 & 0xFFFF0000u);
    float l1 = v.y - __uint_as_float(x1 & 0xFFFF0000u);
    float l2 = v.z - __uint_as_float(x2 & 0xFFFF0000u);
    float l3 = v.w - __uint_as_float(x3 & 0xFFFF0000u);
    uint32_t lo01, lo23;
    asm("prmt.b32 %0, %1, %2, 0x7632;" : "=r"(lo01)
        : "r"(__float_as_uint(l0)), "r"(__float_as_uint(l1)));
    asm("prmt.b32 %0, %1, %2, 0x7632;" : "=r"(lo23)
        : "r"(__float_as_uint(l2)), "r"(__float_as_uint(l3)));
    *(uint2*)hd   = make_uint2(h01, h23);
    *(uint2*)ldst = make_uint2(lo01, lo23);
}

__global__ void __launch_bounds__(256, 3)
k_mm_tc2(const float* __restrict__ A0, const float* __restrict__ x0f,
         float* __restrict__ y0, int n0, int gx0,
         const float* __restrict__ A1, const float* __restrict__ x1f,
         float* __restrict__ y1, int n1) {
    __shared__ __nv_bfloat16 Ah[128 * MALD], Al[128 * MALD];
    __shared__ __nv_bfloat16 Xh[MMKC * MALD], Xl[MMKC * MALD];
    int tid = threadIdx.x;
    int warp = tid >> 5, lane = tid & 31;

    int bx = blockIdx.x;
    const float *A, *x; float* y; int n;
    if (bx < gx0) { A = A0; x = x0f; y = y0; n = n0; }
    else          { A = A1; x = x1f; y = y1; n = n1; bx -= gx0; }
    int m0 = bx * 128;

    int nchunks = (n + MMKC - 1) / MMKC;
    int per = (nchunks + gridDim.y - 1) / gridDim.y;
    int ci0 = blockIdx.y * per;
    int ci1 = min(nchunks, ci0 + per);

    float acc[4][4];
    #pragma unroll
    for (int f = 0; f < 4; f++)
        #pragma unroll
        for (int j = 0; j < 4; j++) acc[f][j] = 0.f;

    uint32_t aAddrH = cvta_s(&Ah[(warp * 16 + (lane & 15)) * MALD + ((lane >> 4) << 3)]);
    uint32_t aAddrL = cvta_s(&Al[(warp * 16 + (lane & 15)) * MALD + ((lane >> 4) << 3)]);
    uint32_t xBaseH = cvta_s(&Xh[(lane & 15) * MALD + ((lane >> 4) << 3)]);
    uint32_t xBaseL = cvta_s(&Xl[(lane & 15) * MALD + ((lane >> 4) << 3)]);

    int ar = tid >> 1, ahalf = tid & 1;
    int xr = tid >> 3, xc = (tid & 7) << 2;
    int gr = m0 + ar;
    const float* Arow = A + (size_t)gr * n + ahalf * 16;

    float4 aR[4], xR;
    const float4 Z4 = make_float4(0.f, 0.f, 0.f, 0.f);
    {
        int k0 = ci0 * MMKC;
        xR = Z4;
        if (k0 + xr < n) xR = *(const float4*)(x + (size_t)(k0 + xr) * 32 + xc);
        #pragma unroll
        for (int j = 0; j < 4; j++) {
            int col = ahalf * 16 + j * 4;
            aR[j] = Z4;
            if (gr < n && (k0 + col + 4) <= n) aR[j] = *(const float4*)(Arow + k0 + j * 4);
        }
    }

    for (int ci = ci0; ci < ci1; ci++) {
        st_split4(xR, &Xh[xr * MALD + xc], &Xl[xr * MALD + xc]);
        #pragma unroll
        for (int j = 0; j < 4; j++) {
            int col = ahalf * 16 + j * 4;
            st_split4(aR[j], &Ah[ar * MALD + col], &Al[ar * MALD + col]);
        }
        __syncthreads();
        if (ci + 1 < ci1) {
            int k0 = (ci + 1) * MMKC;
            xR = Z4;
            if (k0 + xr < n) xR = *(const float4*)(x + (size_t)(k0 + xr) * 32 + xc);
            #pragma unroll
            for (int j = 0; j < 4; j++) {
                int col = ahalf * 16 + j * 4;
                aR[j] = Z4;
                if (gr < n && (k0 + col + 4) <= n) aR[j] = *(const float4*)(Arow + k0 + j * 4);
            }
        }
        #pragma unroll
        for (int ks = 0; ks < MMKC; ks += 16) {
            uint32_t afh[4], afl[4];
            ldm_x4(afh, aAddrH + ks * 2);
            ldm_x4(afl, aAddrL + ks * 2);
            #pragma unroll
            for (int np = 0; np < 2; np++) {
                uint32_t bh[4], bl[4];
                uint32_t off = (uint32_t)(ks * MALD + np * 16) * 2;
                ldm_x4_t(bh, xBaseH + off);
                ldm_x4_t(bl, xBaseL + off);
                mma_bf16(acc[np * 2 + 0], afh, bh[0], bh[1]);
                mma_bf16(acc[np * 2 + 1], afh, bh[2], bh[3]);
                mma_bf16(acc[np * 2 + 0], afh, bl[0], bl[1]);
                mma_bf16(acc[np * 2 + 1], afh, bl[2], bl[3]);
                mma_bf16(acc[np * 2 + 0], afl, bh[0], bh[1]);
                mma_bf16(acc[np * 2 + 1], afl, bh[2], bh[3]);
            }
        }
        __syncthreads();
    }

    int gr8 = lane >> 2, cc = (lane & 3) * 2;
    #pragma unroll
    for (int f = 0; f < 4; f++) {
        int nc = f * 8 + cc;
        int r0 = m0 + warp * 16 + gr8;
        int r1 = r0 + 8;
        if (r0 < n) red2(y + (size_t)r0 * 32 + nc, acc[f][0], acc[f][1]);
        if (r1 < n) red2(y + (size_t)r1 * 32 + nc, acc[f][2], acc[f][3]);
    }
}

// ---------------- group_userlayer: pool over 0.25*(usum+ys+um) ----------------
__global__ void k_gul(float* __restrict__ gul, const int* __restrict__ users,
                      const float* __restrict__ mask, const float* __restrict__ t0,
                      const float* __restrict__ t1, const float* __restrict__ t2) {
    int i = blockIdx.x * blockDim.x + threadIdx.x;
    if (i >= G_N * 32) return;
    int g = i >> 5, d = i & 31;
    float s = 0.f;
    #pragma unroll
    for (int l = 0; l < LM; l++) {
        int u = __ldg(users + g * LM + l);
        size_t o = ((size_t)u << 5) + d;
        float acc = __ldg(t0 + o) + __ldg(t1 + o) + __ldg(t2 + o);
        s = fmaf(__ldg(mask + g * LM + l), acc, s);
    }
    gul[i] = 0.25f * s;
}

// ---------------- gate MLP (one warp per row); g_emb = 0.25*gsum inline ----------------
__global__ void k_gate(float* __restrict__ w, const float* __restrict__ gsum,
                       const float* __restrict__ gul,
                       const float* __restrict__ w1, const float* __restrict__ b1,
                       const float* __restrict__ w2, const float* __restrict__ b2) {
    int wid = (blockIdx.x * blockDim.x + threadIdx.x) >> 5;
    int lane = threadIdx.x & 31;
    if (wid >= 2 * G_N) return;
    float xd = (wid < G_N) ? 0.25f * __ldg(gsum + (size_t)wid * 32 + lane)
                           : __ldg(gul + (size_t)(wid - G_N) * 32 + lane);
    float h = b1[lane];
    #pragma unroll
    for (int d = 0; d < 32; d++) {
        float a = __shfl_sync(0xffffffffu, xd, d);
        h = fmaf(a, __ldg(w1 + d * 32 + lane), h);
    }
    h = fmaxf(h, 0.f);
    float t = h * __ldg(w2 + lane);
    #pragma unroll
    for (int o = 16; o > 0; o >>= 1) t += __shfl_xor_sync(0xffffffffu, t, o);
    if (lane == 0) w[wid] = 1.f / (1.f + expf(-(t + b2[0])));
}

__global__ void k_combine(float* __restrict__ gf, const float* __restrict__ w,
                          const float* __restrict__ gsum, const float* __restrict__ gul) {
    int i = blockIdx.x * blockDim.x + threadIdx.x;
    if (i >= G_N * 32) return;
    int g = i >> 5;
    gf[i] = w[g] * 0.25f * gsum[i] + w[G_N + g] * gul[i];
}

// ---------------- predict MLP; iacc = 0.25*(giis+yi+im) inline ----------------
__global__ void k_pred(float* __restrict__ out, const int* __restrict__ gin,
                       const int* __restrict__ iin, const float* __restrict__ gf,
                       const float* __restrict__ t0, const float* __restrict__ t1,
                       const float* __restrict__ t2,
                       const float* __restrict__ pw1, const float* __restrict__ pb1,
                       const float* __restrict__ pw2, const float* __restrict__ pb2) {
    int wid = (blockIdx.x * blockDim.x + threadIdx.x) >> 5;
    int lane = threadIdx.x & 31;
    if (wid >= B_N) return;
    int g = __ldg(gin + wid), it = __ldg(iin + wid);
    size_t o = ((size_t)it << 5) + lane;
    float ia = 0.25f * (__ldg(t0 + o) + __ldg(t1 + o) + __ldg(t2 + o));
    float e = __ldg(gf + (size_t)g * 32 + lane) * ia;
    float s = 0.f;
    #pragma unroll
    for (int j = 0; j < 8; j++) {
        float p = e * __ldg(pw1 + lane * 8 + j);
        #pragma unroll
        for (int o2 = 16; o2 > 0; o2 >>= 1) p += __shfl_xor_sync(0xffffffffu, p, o2);
        s += fmaxf(p + pb1[j], 0.f) * pw2[j];
    }
    if (lane == 0) out[wid] = 1.f / (1.f + expf(-(s + pb2[0])));
}

// ---------------- host driver ----------------
static inline int cdiv(int a, int b) { return (a + b - 1) / b; }

extern "C" void kernel_launch(void* const* d_in, const int* in_sizes, int n_in,
                              void* d_out, int out_size) {
    const int*   gin  = (const int*)  d_in[0];
    const int*   iin  = (const int*)  d_in[1];
    const float* uemb = (const float*)d_in[2];
    const float* gemb = (const float*)d_in[3];
    const float* iemb = (const float*)d_in[4];
    const int*   ui_r = (const int*)  d_in[5];
    const int*   ui_c = (const int*)  d_in[6];
    const float* ui_v = (const float*)d_in[7];
    const int*   gi_r = (const int*)  d_in[8];
    const int*   gi_c = (const int*)  d_in[9];
    const float* gi_v = (const float*)d_in[10];
    const float* ovu  = (const float*)d_in[11];
    const float* ovi  = (const float*)d_in[12];
    const int*   agu  = (const int*)  d_in[13];
    const float* agm  = (const float*)d_in[14];
    const float* gw1  = (const float*)d_in[15];
    const float* gb1  = (const float*)d_in[16];
    const float* gw2  = (const float*)d_in[17];
    const float* gb2  = (const float*)d_in[18];
    const float* pw1  = (const float*)d_in[19];
    const float* pb1  = (const float*)d_in[20];
    const float* pw2  = (const float*)d_in[21];
    const float* pb2  = (const float*)d_in[22];
    float* out = (float*)d_out;
    const int nnz_ui = in_sizes[5];
    const int nnz_gi = in_sizes[8];

    float* S = nullptr;
    cudaGetSymbolAddress((void**)&S, d_scratch);

    const int TPB = 256;
    #define F4(off)  ((float4*)(S + (off)))
    #define CF4(p)   ((const float4*)(p))

    int spmm_ui_grid = cdiv(nnz_ui * 8, TPB);
    int spmm_gi_grid = cdiv(nnz_gi * 8, TPB);

    // ======== UI graph conv: 3 layers, sums fused into spmm ========
    k_copy2<<<cdiv(144000,TPB),TPB>>>(F4(OFF_USUM), CF4(uemb), 80000,
                                      F4(OFF_ISUM), CF4(iemb), 64000);
    k_zero4<<<cdiv(288000,TPB),TPB>>>(F4(OFF_UI_A), 288000);
    k_spmm<<<spmm_ui_grid,TPB>>>(ui_r, ui_c, ui_v, nnz_ui, uemb, iemb, U_N,
                                 S + OFF_UI_B, U_N + I_N, S + OFF_USUM, 0);
    k_spmm<<<spmm_ui_grid,TPB>>>(ui_r, ui_c, ui_v, nnz_ui,
                                 S + OFF_UI_B, S + OFF_UI_B + U_N*32, U_N,
                                 S + OFF_UI_A, U_N + I_N, S + OFF_USUM, 0);
    k_zero4<<<cdiv(144000,TPB),TPB>>>(F4(OFF_UI_B), 144000);
    k_spmm<<<spmm_ui_grid,TPB>>>(ui_r, ui_c, ui_v, nnz_ui,
                                 S + OFF_UI_A, S + OFF_UI_A + U_N*32, U_N,
                                 S + OFF_UI_B, U_N + I_N, S + OFF_USUM, 0);

    // IEU = 0.25*ISUM (spmm input), GIIS initialized to same value
    k_scale_dup4<<<cdiv(64000,TPB),TPB>>>(F4(OFF_IEU), F4(OFF_GIIS),
                                          CF4(S + OFF_ISUM), 0.25f, 64000);
    k_copy4<<<cdiv(24000,TPB),TPB>>>(F4(OFF_GSUM), CF4(gemb), 24000);

    // ======== GI graph conv (sums fused; GSUM|GIIS covers rows 0..11000) ========
    k_zero4<<<cdiv(176000,TPB),TPB>>>(F4(OFF_GI_A), 176000);
    k_spmm<<<spmm_gi_grid,TPB>>>(gi_r, gi_c, gi_v, nnz_gi, gemb, S + OFF_IEU, G_N,
                                 S + OFF_GI_B, G_N + I_N, S + OFF_GSUM, G_N);
    k_spmm<<<spmm_gi_grid,TPB>>>(gi_r, gi_c, gi_v, nnz_gi,
                                 S + OFF_GI_B, S + OFF_GI_B + G_N*32, G_N,
                                 S + OFF_GI_A, G_N + I_N, S + OFF_GSUM, 0);
    k_zero4<<<cdiv(88000,TPB),TPB>>>(F4(OFF_GI_B), 88000);
    k_spmm<<<spmm_gi_grid,TPB>>>(gi_r, gi_c, gi_v, nnz_gi,
                                 S + OFF_GI_A, S + OFF_GI_A + G_N*32, G_N,
                                 S + OFF_GI_B, G_N + I_N, S + OFF_GSUM, G_N);
    // g_layers[1] and g_layers[3] red straight into GSUM (rows < G only)
    k_spmm<<<spmm_gi_grid,TPB>>>(gi_r, gi_c, gi_v, nnz_gi, gemb, iemb, G_N,
                                 S + OFF_GSUM, G_N, nullptr, 0);
    k_spmm<<<spmm_gi_grid,TPB>>>(gi_r, gi_c, gi_v, nnz_gi, gemb, S + OFF_UI_A + U_N*32,
                                 G_N, S + OFF_GSUM, G_N, nullptr, 0);

    // ======== social power series: fused user+item MM per hop ========
    // terms kept unscaled; 0.25 folded into k_gul / k_pred.
    // zero UM (80000 f4) and IM|YS contiguous range (144000 f4)
    k_zero2buf<<<cdiv(224000,TPB),TPB>>>(F4(OFF_UM), 80000, F4(OFF_IM), 144000);
    k_zero4<<<cdiv(64000,TPB),TPB>>>(F4(OFF_YI), 64000);
    int gxU = cdiv(U_N, 128), gxI = cdiv(I_N, 128);
    dim3 gmm(gxU + gxI, 8);
    // hop 1: YS = ovu@USUM ; YI = ovi@GIIS
    k_mm_tc2<<<gmm,256>>>(ovu, S + OFF_USUM, S + OFF_YS, U_N, gxU,
                          ovi, S + OFF_GIIS, S + OFF_YI, I_N);
    // hop 2: UM = ovu@YS ; IM = ovi@YI
    k_mm_tc2<<<gmm,256>>>(ovu, S + OFF_YS, S + OFF_UM, U_N, gxU,
                          ovi, S + OFF_YI, S + OFF_IM, I_N);

    // ======== pooling, gate, predict ========
    k_gul<<<cdiv(G_N*32, TPB), TPB>>>(S + OFF_GUL, agu, agm,
                                      S + OFF_USUM, S + OFF_YS, S + OFF_UM);
    k_gate<<<cdiv(2*G_N*32, TPB), TPB>>>(S + OFF_W, S + OFF_GSUM, S + OFF_GUL,
                                         gw1, gb1, gw2, gb2);
    k_combine<<<cdiv(G_N*32, TPB), TPB>>>(S + OFF_GF, S + OFF_W, S + OFF_GSUM, S + OFF_GUL);
    k_pred<<<cdiv(B_N*32, TPB), TPB>>>(out, gin, iin, S + OFF_GF,
                                       S + OFF_GIIS, S + OFF_YI, S + OFF_IM,
                                       pw1, pb1, pw2, pb2);
    #undef F4
    #undef CF4
}